// round 11
// baseline (speedup 1.0000x reference)
#include <cuda_runtime.h>
#include <cstddef>
#include <math_constants.h>

#define NNODES 4096
#define NB 4
#define BN (NNODES * NB)
#define DFEAT 240
#define FXSTRIDE 256
#define KNN 8
#define KTHREADS 512
#define KWARPS (KTHREADS / 32)

// Scratch (allocation-free rule: __device__ globals)
__device__ int    g_knn[BN * KNN];
__device__ float4 g_c4[BN];                       // (x,y,z,|c|^2/2)
__device__ float  g_fx[(size_t)BN * FXSTRIDE];    // repacked features
// Fused (W @ L) matrices, output scales baked in
__device__ float g_WL0[32 * 64];   // (W2@L0)  * c2/8
__device__ float g_WL1a[64 * 32];  // (W1@L1)  * c1/sqrt(32)
__device__ float g_WL1b[16 * 32];  // (W4@L1)  * c4/sqrt(32)
__device__ float g_WL2[32 * 16];   // (W3@L2)  * c3/4

// T[a][k] = (Cm[a] . ev)[k], Cm = real Wigner 1x1->2 coupling / sqrt(5)
__device__ __forceinline__ void compute_T(float ex, float ey, float ez, float T[5][3]) {
    const float sc = 0.31622776601683794f;   // 1/sqrt(2)/sqrt(5)
    const float tc = 0.18257418583505536f;   // 1/sqrt(6)/sqrt(5)
    T[0][0] = sc * ey;  T[0][1] = sc * ex;   T[0][2] = 0.f;
    T[1][0] = sc * ez;  T[1][1] = 0.f;       T[1][2] = sc * ex;
    T[2][0] = 0.f;      T[2][1] = sc * ez;   T[2][2] = sc * ey;
    T[3][0] = sc * ex;  T[3][1] = -sc * ey;  T[3][2] = 0.f;
    T[4][0] = -tc * ex; T[4][1] = -tc * ey;  T[4][2] = 2.f * tc * ez;
}

// ============================================================================
// Kernel 0: repack features per node (warp per node) + build g_c4.
// Layout per node (stride 256 floats):
//   [4u .. 4u+4)   = (x0[u], x1[u][0], x1[u][1], x1[u][2])   u<32  (LDG.128)
//   [128 + u)      = x0[32+u]                                 u<32
//   [160 + 4u ..)  = x2[u][0..3]                              u<16  (LDG.128)
//   [224 + u)      = x2[u][4]                                 u<16
// ============================================================================
__global__ __launch_bounds__(256) void repack_kernel(
    const float* __restrict__ feats, const float* __restrict__ coords) {
    int warp = threadIdx.x >> 5, lane = threadIdx.x & 31;
    int node = blockIdx.x * 8 + warp;
    const float* f = feats + (size_t)node * DFEAT;
    float* o = g_fx + (size_t)node * FXSTRIDE;
    float4 A;
    A.x = f[lane];
    A.y = f[64 + 3 * lane];
    A.z = f[64 + 3 * lane + 1];
    A.w = f[64 + 3 * lane + 2];
    *(float4*)(o + 4 * lane) = A;
    o[128 + lane] = f[32 + lane];
    if (lane < 16) {
        float4 X;
        X.x = f[160 + 5 * lane];
        X.y = f[160 + 5 * lane + 1];
        X.z = f[160 + 5 * lane + 2];
        X.w = f[160 + 5 * lane + 3];
        *(float4*)(o + 160 + 4 * lane) = X;
        o[224 + lane] = f[160 + 5 * lane + 4];
    }
    if (threadIdx.x < 8) {                        // g_c4 for this block's 8 nodes
        int n2 = blockIdx.x * 8 + threadIdx.x;
        float x = coords[3 * n2], y = coords[3 * n2 + 1], z = coords[3 * n2 + 2];
        g_c4[n2] = make_float4(x, y, z, 0.5f * fmaf(x, x, fmaf(y, y, z * z)));
    }
}

// ============================================================================
// Kernel 1: kNN, WARP per query, TOP-9 distributed across lanes 0..8 (sorted
// ascending; lane 8 = worst). No per-candidate self-exclusion: the query
// itself has the strict unique minimum score (-|q|^2/2), so it provably ends
// in lane 0; lanes 1..8 are the true top-8 neighbors. Per step: 256
// candidates (8/lane) from shared tile, ONE warp-uniform vote; inserts are
// warp-uniform shfl-shift ops. Tie = earliest index (ballot low->high =
// index order; strict > keeps earlier equal values ahead) — matches top_k.
// ============================================================================
__global__ __launch_bounds__(KTHREADS) void knn_kernel() {
    __shared__ float4 tile[2048];                 // 32KB (chunked: 2 x 2048)
    const unsigned FULL = 0xffffffffu;
    int b = blockIdx.y;
    int warp = threadIdx.x >> 5, lane = threadIdx.x & 31;
    int q = blockIdx.x * KWARPS + warp;           // query within batch
    int qflat = b * NNODES + q;

    float4 qc = g_c4[qflat];
    float nqx = -qc.x, nqy = -qc.y, nqz = -qc.z;

    float v  = CUDART_INF_F;                      // lane's slot of the top-9 (lanes 0..8)
    int  vid = 0x7fffffff;
    float worst = CUDART_INF_F;                   // = v at lane 8

    for (int ch = 0; ch < 2; ch++) {
        int cbase = ch << 11;
        __syncthreads();
        for (int k = threadIdx.x; k < 2048; k += KTHREADS)
            tile[k] = g_c4[b * NNODES + cbase + k];
        __syncthreads();

        for (int s = 0; s < 2048; s += 256) {
            float d[8];
#pragma unroll
            for (int t = 0; t < 8; t++) {
                float4 c = tile[s + (t << 5) + lane];
                d[t] = fmaf(nqx, c.x, fmaf(nqy, c.y, fmaf(nqz, c.z, c.w)));
            }
            float m01 = fminf(d[0], d[1]), m23 = fminf(d[2], d[3]);
            float m45 = fminf(d[4], d[5]), m67 = fminf(d[6], d[7]);
            float m = fminf(fminf(m01, m23), fminf(m45, m67));
            if (__any_sync(FULL, m < worst)) {
#pragma unroll
                for (int t = 0; t < 8; t++) {
                    unsigned mask = __ballot_sync(FULL, d[t] < worst);
                    int jbase = cbase + s + (t << 5);
                    while (mask) {
                        int src = __ffs(mask) - 1; mask &= mask - 1;
                        float nb = __shfl_sync(FULL, d[t], src);
                        if (nb < worst) {                 // warp-uniform recheck
                            int ib = jbase + src;
                            unsigned gt = __ballot_sync(FULL, (lane < 9) && (v > nb));
                            int p = __ffs(gt) - 1;        // nonzero: lane8 has v=worst>nb
                            float vup = __shfl_up_sync(FULL, v, 1);
                            int  iup  = __shfl_up_sync(FULL, vid, 1);
                            if (lane == p)                 { v = nb;  vid = ib;  }
                            else if (lane > p && lane < 9) { v = vup; vid = iup; }
                            worst = __shfl_sync(FULL, v, 8);
                        }
                    }
                }
            }
        }
    }

    if (lane >= 1 && lane < 9)                    // lane 0 = self; drop it
        g_knn[qflat * KNN + (lane - 1)] = b * NNODES + vid;
}

// ============================================================================
// Kernel 2: fuse W and L matrices (W commutes with aggregation) + bake scales.
// ============================================================================
__global__ __launch_bounds__(256) void fuse_kernel(
    const float* __restrict__ W1, const float* __restrict__ W2,
    const float* __restrict__ W3, const float* __restrict__ W4,
    const float* __restrict__ L0, const float* __restrict__ L1,
    const float* __restrict__ L2) {
    const float c1 = 0.11180339887498949f;   // sqrt(1/80)
    const float c2 = 0.10206207261596575f;   // sqrt(1/96)
    const float c3 = 0.39528470752104744f;   // sqrt(5/32)
    const float c4 = 0.19364916731037085f;   // sqrt(3/80)
    const float is32 = 0.17677669529663687f; // 1/sqrt(32)
    int idx = blockIdx.x * 256 + threadIdx.x;
    if (idx < 2048) {                         // WL0 = W2@L0 : (32,64)
        int u = idx >> 6, w2 = idx & 63;
        float acc = 0.f;
        for (int w = 0; w < 64; w++) acc = fmaf(W2[u * 64 + w], L0[w * 64 + w2], acc);
        g_WL0[idx] = (c2 * 0.125f) * acc;
    } else if (idx < 4096) {                  // WL1a = W1@L1 : (64,32)
        int t = idx - 2048, u = t >> 5, w2 = t & 31;
        float acc = 0.f;
        for (int w = 0; w < 32; w++) acc = fmaf(W1[u * 32 + w], L1[w * 32 + w2], acc);
        g_WL1a[t] = (c1 * is32) * acc;
    } else if (idx < 4608) {                  // WL1b = W4@L1 : (16,32)
        int t = idx - 4096, u = t >> 5, w2 = t & 31;
        float acc = 0.f;
        for (int w = 0; w < 32; w++) acc = fmaf(W4[u * 32 + w], L1[w * 32 + w2], acc);
        g_WL1b[t] = (c4 * is32) * acc;
    } else {                                  // WL2 = W3@L2 : (32,16)
        int t = idx - 4608, u = t >> 4, w2 = t & 15;
        float acc = 0.f;
        for (int w = 0; w < 16; w++) acc = fmaf(W3[u * 16 + w], L2[w * 16 + w2], acc);
        g_WL2[t] = (c3 * 0.25f) * acc;
    }
}

// ============================================================================
// Kernel 3: fused aggregation. Warp per node. SOFTWARE-PIPELINED edge loop:
// edge r+1's gathered loads (features + coords) are issued before edge r's
// compute, doubling load->use distance (latency hidden by ILP, not just
// occupancy). Fused WL linears from shared at the end.
// ============================================================================
__global__ __launch_bounds__(256) void agg_kernel(float* __restrict__ out) {
    __shared__ float sWL0[2048], sWL1a[2048], sWL1b[512], sWL2[512];
    __shared__ float sag[8][440];
    for (int k = threadIdx.x; k < 2048; k += 256) { sWL0[k] = g_WL0[k]; sWL1a[k] = g_WL1a[k]; }
    for (int k = threadIdx.x; k < 512;  k += 256) { sWL1b[k] = g_WL1b[k]; sWL2[k] = g_WL2[k]; }

    int warp = threadIdx.x >> 5, lane = threadIdx.x & 31;
    int node = (blockIdx.x << 3) + warp;
    float4 qc = g_c4[node];

    // front-batch neighbor ids (32B aligned)
    int4 n0 = *(const int4*)(g_knn + node * KNN);
    int4 n1 = *(const int4*)(g_knn + node * KNN + 4);
    int nbr[8] = {n0.x, n0.y, n0.z, n0.w, n1.x, n1.y, n1.z, n1.w};

    float a0 = 0.f;
    float a1a0[3] = {0.f, 0.f, 0.f};
    float a1a1[3] = {0.f, 0.f, 0.f};
    float a1b[3]  = {0.f, 0.f, 0.f};
    float a2[5]   = {0.f, 0.f, 0.f, 0.f, 0.f};

    // ---- pipeline prologue: edge 0 loads
    const float* f0p = g_fx + (size_t)nbr[0] * FXSTRIDE;
    float4 A  = *(const float4*)(f0p + 4 * lane);
    float f0b = f0p[128 + lane];
    float4 X  = make_float4(0.f, 0.f, 0.f, 0.f);
    float x4  = 0.f;
    if (lane < 16) {
        X  = *(const float4*)(f0p + 160 + 4 * lane);
        x4 = f0p[224 + lane];
    }
    float4 cn = g_c4[nbr[0]];

#pragma unroll
    for (int r = 0; r < KNN; r++) {
        // consume current stage
        float4 Ac = A; float f0bc = f0b; float4 Xc = X; float x4c = x4; float4 cnc = cn;
        // issue next stage loads (in flight during this edge's compute)
        if (r < KNN - 1) {
            const float* fn = g_fx + (size_t)nbr[r + 1] * FXSTRIDE;
            A   = *(const float4*)(fn + 4 * lane);
            f0b = fn[128 + lane];
            if (lane < 16) {
                X  = *(const float4*)(fn + 160 + 4 * lane);
                x4 = fn[224 + lane];
            }
            cn = g_c4[nbr[r + 1]];
        }

        float e[3] = {cnc.x - qc.x, cnc.y - qc.y, cnc.z - qc.z};
        float T[5][3];
        compute_T(e[0], e[1], e[2], T);
        float x1v[3] = {Ac.y, Ac.z, Ac.w};
        float x2v[5] = {Xc.x, Xc.y, Xc.z, Xc.w, x4c};

#pragma unroll
        for (int k = 0; k < 3; k++) {
            a1a0[k] = fmaf(Ac.x,  e[k], a1a0[k]);
            a1a1[k] = fmaf(f0bc, e[k], a1a1[k]);
        }
#pragma unroll
        for (int i = 0; i < 3; i++) a0 = fmaf(x1v[i], e[i], a0);
#pragma unroll
        for (int a = 0; a < 5; a++)
#pragma unroll
            for (int i = 0; i < 3; i++) a2[a] = fmaf(x1v[i], T[a][i], a2[a]);
        if (lane < 16) {
#pragma unroll
            for (int a = 0; a < 5; a++)
#pragma unroll
                for (int k = 0; k < 3; k++) a1b[k] = fmaf(x2v[a], T[a][k], a1b[k]);
        }
    }

    __syncthreads();   // sWL ready

    // stage aggregates: [0,32) a0 | 32+3u+k (u<64) a1a | 224+3u+k (u<16) a1b | 272+5u+a a2
    float* ag = sag[warp];
    ag[lane] = a0;
#pragma unroll
    for (int k = 0; k < 3; k++) {
        ag[32 + 3 * lane + k]        = a1a0[k];
        ag[32 + 3 * (lane + 32) + k] = a1a1[k];
    }
    if (lane < 16) {
#pragma unroll
        for (int k = 0; k < 3; k++) ag[224 + 3 * lane + k] = a1b[k];
    }
#pragma unroll
    for (int a = 0; a < 5; a++) ag[272 + 5 * lane + a] = a2[a];
    __syncwarp();

    float* o = out + (size_t)node * DFEAT;
    {   // y0[w'] = sum_u a0[u] WL0[u,w']   (w' = 2lane, 2lane+1)
        float y0 = 0.f, y1v = 0.f;
#pragma unroll
        for (int u = 0; u < 32; u++) {
            float av = ag[u];
            y0  = fmaf(av, sWL0[u * 64 + 2 * lane],     y0);
            y1v = fmaf(av, sWL0[u * 64 + 2 * lane + 1], y1v);
        }
        o[2 * lane]     = y0;
        o[2 * lane + 1] = y1v;
    }
    {   // y1[w',k] = sum_{u<64} a1a[u,k] WL1a[u,w'] + sum_{u<16} a1b[u,k] WL1b[u,w']
        float y[3] = {0.f, 0.f, 0.f};
#pragma unroll
        for (int u = 0; u < 64; u++) {
            float lw = sWL1a[u * 32 + lane];
#pragma unroll
            for (int k = 0; k < 3; k++) y[k] = fmaf(ag[32 + 3 * u + k], lw, y[k]);
        }
#pragma unroll
        for (int u = 0; u < 16; u++) {
            float lw = sWL1b[u * 32 + lane];
#pragma unroll
            for (int k = 0; k < 3; k++) y[k] = fmaf(ag[224 + 3 * u + k], lw, y[k]);
        }
#pragma unroll
        for (int k = 0; k < 3; k++) o[64 + 3 * lane + k] = y[k];
    }
    if (lane < 16) {   // y2[w',a] = sum_u a2[u,a] WL2[u,w']
        float y[5] = {0.f, 0.f, 0.f, 0.f, 0.f};
#pragma unroll
        for (int u = 0; u < 32; u++) {
            float lw = sWL2[u * 16 + lane];
#pragma unroll
            for (int a = 0; a < 5; a++) y[a] = fmaf(ag[272 + 5 * u + a], lw, y[a]);
        }
#pragma unroll
        for (int a = 0; a < 5; a++) o[160 + 5 * lane + a] = y[a];
    }
}

// ============================================================================
extern "C" void kernel_launch(void* const* d_in, const int* in_sizes, int n_in,
                              void* d_out, int out_size) {
    const float* feats  = (const float*)d_in[0];  // (4,4096,240)
    const float* coords = (const float*)d_in[1];  // (4,4096,3)
    const float* W1 = (const float*)d_in[2];      // (64,32)
    const float* W2 = (const float*)d_in[3];      // (32,64)
    const float* W3 = (const float*)d_in[4];      // (32,16)
    const float* W4 = (const float*)d_in[5];      // (16,32)
    const float* L0 = (const float*)d_in[6];      // (64,64)
    const float* L1 = (const float*)d_in[7];      // (32,32)
    const float* L2 = (const float*)d_in[8];      // (16,16)
    float* out = (float*)d_out;

    repack_kernel<<<BN / 8, 256>>>(feats, coords);
    fuse_kernel<<<20, 256>>>(W1, W2, W3, W4, L0, L1, L2);
    knn_kernel<<<dim3(NNODES / KWARPS, NB), KTHREADS>>>();
    agg_kernel<<<BN / 8, 256>>>(out);
}

// round 12
// speedup vs baseline: 1.0354x; 1.0354x over previous
#include <cuda_runtime.h>
#include <cstddef>
#include <math_constants.h>

#define NNODES 4096
#define NB 4
#define BN (NNODES * NB)
#define DFEAT 240
#define FXSTRIDE 256
#define KNN 8
#define KTHREADS 512
#define KWARPS (KTHREADS / 32)

// Scratch (allocation-free rule: __device__ globals)
__device__ int    g_knn[BN * KNN];
__device__ float4 g_c4[BN];                       // (x,y,z,|c|^2/2)
__device__ float  g_fx[(size_t)BN * FXSTRIDE];    // repacked features
// Fused (W @ L) matrices, output scales baked in
__device__ float g_WL0[32 * 64];   // (W2@L0)  * c2/8
__device__ float g_WL1a[64 * 32];  // (W1@L1)  * c1/sqrt(32)
__device__ float g_WL1b[16 * 32];  // (W4@L1)  * c4/sqrt(32)
__device__ float g_WL2[32 * 16];   // (W3@L2)  * c3/4

// T[a][k] = (Cm[a] . ev)[k], Cm = real Wigner 1x1->2 coupling / sqrt(5)
__device__ __forceinline__ void compute_T(float ex, float ey, float ez, float T[5][3]) {
    const float sc = 0.31622776601683794f;   // 1/sqrt(2)/sqrt(5)
    const float tc = 0.18257418583505536f;   // 1/sqrt(6)/sqrt(5)
    T[0][0] = sc * ey;  T[0][1] = sc * ex;   T[0][2] = 0.f;
    T[1][0] = sc * ez;  T[1][1] = 0.f;       T[1][2] = sc * ex;
    T[2][0] = 0.f;      T[2][1] = sc * ez;   T[2][2] = sc * ey;
    T[3][0] = sc * ex;  T[3][1] = -sc * ey;  T[3][2] = 0.f;
    T[4][0] = -tc * ex; T[4][1] = -tc * ey;  T[4][2] = 2.f * tc * ez;
}

// ============================================================================
// Kernel 0: repack features per node (warp per node) + build g_c4.
// Layout per node (stride 256 floats):
//   [4u .. 4u+4)   = (x0[u], x1[u][0], x1[u][1], x1[u][2])   u<32  (LDG.128)
//   [128 + u)      = x0[32+u]                                 u<32
//   [160 + 4u ..)  = x2[u][0..3]                              u<16  (LDG.128)
//   [224 + u)      = x2[u][4]                                 u<16
// ============================================================================
__global__ __launch_bounds__(256) void repack_kernel(
    const float* __restrict__ feats, const float* __restrict__ coords) {
    int warp = threadIdx.x >> 5, lane = threadIdx.x & 31;
    int node = blockIdx.x * 8 + warp;
    const float* f = feats + (size_t)node * DFEAT;
    float* o = g_fx + (size_t)node * FXSTRIDE;
    float4 A;
    A.x = f[lane];
    A.y = f[64 + 3 * lane];
    A.z = f[64 + 3 * lane + 1];
    A.w = f[64 + 3 * lane + 2];
    *(float4*)(o + 4 * lane) = A;
    o[128 + lane] = f[32 + lane];
    if (lane < 16) {
        float4 X;
        X.x = f[160 + 5 * lane];
        X.y = f[160 + 5 * lane + 1];
        X.z = f[160 + 5 * lane + 2];
        X.w = f[160 + 5 * lane + 3];
        *(float4*)(o + 160 + 4 * lane) = X;
        o[224 + lane] = f[160 + 5 * lane + 4];
    }
    if (threadIdx.x < 8) {                        // g_c4 for this block's 8 nodes
        int n2 = blockIdx.x * 8 + threadIdx.x;
        float x = coords[3 * n2], y = coords[3 * n2 + 1], z = coords[3 * n2 + 2];
        g_c4[n2] = make_float4(x, y, z, 0.5f * fmaf(x, x, fmaf(y, y, z * z)));
    }
}

// ============================================================================
// Kernel 1: kNN, WARP per query, TOP-9 distributed across lanes 0..8 (sorted
// ascending; lane 8 = worst). No per-candidate self-exclusion: the query
// itself has the strict unique minimum score (-|q|^2/2), so it provably ends
// in lane 0; lanes 1..8 are the true top-8 neighbors. Per step: 128
// candidates (4/lane) from shared tile, one warp-uniform vote; inserts are
// warp-uniform shfl-shift ops. Tie = earliest index — matches top_k.
// ============================================================================
__global__ __launch_bounds__(KTHREADS) void knn_kernel() {
    __shared__ float4 tile[2048];                 // 32KB (chunked: 2 x 2048)
    const unsigned FULL = 0xffffffffu;
    int b = blockIdx.y;
    int warp = threadIdx.x >> 5, lane = threadIdx.x & 31;
    int q = blockIdx.x * KWARPS + warp;           // query within batch
    int qflat = b * NNODES + q;

    float4 qc = g_c4[qflat];
    float nqx = -qc.x, nqy = -qc.y, nqz = -qc.z;

    float v  = CUDART_INF_F;                      // lane's slot of the top-9 (lanes 0..8)
    int  vid = 0x7fffffff;
    float worst = CUDART_INF_F;                   // = v at lane 8

    for (int ch = 0; ch < 2; ch++) {
        int cbase = ch << 11;
        __syncthreads();
        for (int k = threadIdx.x; k < 2048; k += KTHREADS)
            tile[k] = g_c4[b * NNODES + cbase + k];
        __syncthreads();

        for (int s = 0; s < 2048; s += 128) {
            float d[4];
#pragma unroll
            for (int t = 0; t < 4; t++) {
                float4 c = tile[s + (t << 5) + lane];
                d[t] = fmaf(nqx, c.x, fmaf(nqy, c.y, fmaf(nqz, c.z, c.w)));
            }
            float m = fminf(fminf(d[0], d[1]), fminf(d[2], d[3]));
            if (__any_sync(FULL, m < worst)) {
#pragma unroll
                for (int t = 0; t < 4; t++) {
                    unsigned mask = __ballot_sync(FULL, d[t] < worst);
                    int jbase = cbase + s + (t << 5);
                    while (mask) {
                        int src = __ffs(mask) - 1; mask &= mask - 1;
                        float nb = __shfl_sync(FULL, d[t], src);
                        if (nb < worst) {                 // warp-uniform recheck
                            int ib = jbase + src;
                            unsigned gt = __ballot_sync(FULL, (lane < 9) && (v > nb));
                            int p = __ffs(gt) - 1;        // nonzero: lane8 has v=worst>nb
                            float vup = __shfl_up_sync(FULL, v, 1);
                            int  iup  = __shfl_up_sync(FULL, vid, 1);
                            if (lane == p)                 { v = nb;  vid = ib;  }
                            else if (lane > p && lane < 9) { v = vup; vid = iup; }
                            worst = __shfl_sync(FULL, v, 8);
                        }
                    }
                }
            }
        }
    }

    if (lane >= 1 && lane < 9)                    // lane 0 = self; drop it
        g_knn[qflat * KNN + (lane - 1)] = b * NNODES + vid;
}

// ============================================================================
// Kernel 2: fuse W and L matrices (W commutes with aggregation) + bake scales.
// ============================================================================
__global__ __launch_bounds__(256) void fuse_kernel(
    const float* __restrict__ W1, const float* __restrict__ W2,
    const float* __restrict__ W3, const float* __restrict__ W4,
    const float* __restrict__ L0, const float* __restrict__ L1,
    const float* __restrict__ L2) {
    const float c1 = 0.11180339887498949f;   // sqrt(1/80)
    const float c2 = 0.10206207261596575f;   // sqrt(1/96)
    const float c3 = 0.39528470752104744f;   // sqrt(5/32)
    const float c4 = 0.19364916731037085f;   // sqrt(3/80)
    const float is32 = 0.17677669529663687f; // 1/sqrt(32)
    int idx = blockIdx.x * 256 + threadIdx.x;
    if (idx < 2048) {                         // WL0 = W2@L0 : (32,64)
        int u = idx >> 6, w2 = idx & 63;
        float acc = 0.f;
        for (int w = 0; w < 64; w++) acc = fmaf(W2[u * 64 + w], L0[w * 64 + w2], acc);
        g_WL0[idx] = (c2 * 0.125f) * acc;
    } else if (idx < 4096) {                  // WL1a = W1@L1 : (64,32)
        int t = idx - 2048, u = t >> 5, w2 = t & 31;
        float acc = 0.f;
        for (int w = 0; w < 32; w++) acc = fmaf(W1[u * 32 + w], L1[w * 32 + w2], acc);
        g_WL1a[t] = (c1 * is32) * acc;
    } else if (idx < 4608) {                  // WL1b = W4@L1 : (16,32)
        int t = idx - 4096, u = t >> 5, w2 = t & 31;
        float acc = 0.f;
        for (int w = 0; w < 32; w++) acc = fmaf(W4[u * 32 + w], L1[w * 32 + w2], acc);
        g_WL1b[t] = (c4 * is32) * acc;
    } else {                                  // WL2 = W3@L2 : (32,16)
        int t = idx - 4608, u = t >> 4, w2 = t & 15;
        float acc = 0.f;
        for (int w = 0; w < 16; w++) acc = fmaf(W3[u * 16 + w], L2[w * 16 + w2], acc);
        g_WL2[t] = (c3 * 0.25f) * acc;
    }
}

// ============================================================================
// Kernel 3: fused aggregation. Warp per node (round-10 edge loop, 48 regs).
// Final linears restructured to minimize LDS instruction count:
//   - aggregates staged at stride-4 (a1a/a1b) -> one broadcast LDS.128 per u
//   - WL0 pair reads as LDS.64
//   - y2 u-loop split across half-warps + shfl reduce
// sag layout per warp (512 floats):
//   [0,32)   a0[u]
//   [32+4u+k)       a1a[u][k]  u<64
//   [288+4u+k)      a1b[u][k]  u<16
//   [352+5u+a)      a2[u][a]   u<32
// ============================================================================
__global__ __launch_bounds__(256) void agg_kernel(float* __restrict__ out) {
    __shared__ float sWL0[2048], sWL1a[2048], sWL1b[512], sWL2[512];
    __shared__ float sag[8][512];
    for (int k = threadIdx.x; k < 2048; k += 256) { sWL0[k] = g_WL0[k]; sWL1a[k] = g_WL1a[k]; }
    for (int k = threadIdx.x; k < 512;  k += 256) { sWL1b[k] = g_WL1b[k]; sWL2[k] = g_WL2[k]; }

    const unsigned FULL = 0xffffffffu;
    int warp = threadIdx.x >> 5, lane = threadIdx.x & 31;
    int node = (blockIdx.x << 3) + warp;
    float4 qc = g_c4[node];

    // front-batch neighbor ids (32B aligned) and edge vectors
    int4 n0 = *(const int4*)(g_knn + node * KNN);
    int4 n1 = *(const int4*)(g_knn + node * KNN + 4);
    int nbr[8] = {n0.x, n0.y, n0.z, n0.w, n1.x, n1.y, n1.z, n1.w};
    float ex[8], ey[8], ez[8];
#pragma unroll
    for (int r = 0; r < 8; r++) {
        float4 cn = g_c4[nbr[r]];
        ex[r] = cn.x - qc.x;
        ey[r] = cn.y - qc.y;
        ez[r] = cn.z - qc.z;
    }

    float a0 = 0.f;
    float a1a0[3] = {0.f, 0.f, 0.f};
    float a1a1[3] = {0.f, 0.f, 0.f};
    float a1b[3]  = {0.f, 0.f, 0.f};
    float a2[5]   = {0.f, 0.f, 0.f, 0.f, 0.f};

#pragma unroll
    for (int r = 0; r < KNN; r++) {
        const float* f = g_fx + (size_t)nbr[r] * FXSTRIDE;
        float4 A = *(const float4*)(f + 4 * lane);        // x0a, x1[0..2]
        float f0b = f[128 + lane];                        // x0b
        float4 X = make_float4(0.f, 0.f, 0.f, 0.f);
        float x4 = 0.f;
        if (lane < 16) {
            X  = *(const float4*)(f + 160 + 4 * lane);    // x2[0..3]
            x4 = f[224 + lane];                           // x2[4]
        }

        float T[5][3];
        compute_T(ex[r], ey[r], ez[r], T);
        float e[3] = {ex[r], ey[r], ez[r]};
        float x1v[3] = {A.y, A.z, A.w};
        float x2v[5] = {X.x, X.y, X.z, X.w, x4};

#pragma unroll
        for (int k = 0; k < 3; k++) {
            a1a0[k] = fmaf(A.x, e[k], a1a0[k]);
            a1a1[k] = fmaf(f0b, e[k], a1a1[k]);
        }
#pragma unroll
        for (int i = 0; i < 3; i++) a0 = fmaf(x1v[i], e[i], a0);
#pragma unroll
        for (int a = 0; a < 5; a++)
#pragma unroll
            for (int i = 0; i < 3; i++) a2[a] = fmaf(x1v[i], T[a][i], a2[a]);
        if (lane < 16) {
#pragma unroll
            for (int a = 0; a < 5; a++)
#pragma unroll
                for (int k = 0; k < 3; k++) a1b[k] = fmaf(x2v[a], T[a][k], a1b[k]);
        }
    }

    __syncthreads();   // sWL ready

    // stage aggregates (padded layout; slot 32+4u+3 / 288+4u+3 unused)
    float* ag = sag[warp];
    ag[lane] = a0;
#pragma unroll
    for (int k = 0; k < 3; k++) {
        ag[32 + 4 * lane + k]          = a1a0[k];
        ag[32 + 4 * (lane + 32) + k]   = a1a1[k];
    }
    if (lane < 16) {
#pragma unroll
        for (int k = 0; k < 3; k++) ag[288 + 4 * lane + k] = a1b[k];
    }
#pragma unroll
    for (int a = 0; a < 5; a++) ag[352 + 5 * lane + a] = a2[a];
    __syncwarp();

    float* o = out + (size_t)node * DFEAT;
    {   // y0[w'] = sum_u a0[u] WL0[u,w']   (w' = 2lane, 2lane+1)
        float y0 = 0.f, y1v = 0.f;
#pragma unroll
        for (int u4 = 0; u4 < 8; u4++) {
            float4 av = *(const float4*)(ag + 4 * u4);            // broadcast LDS.128
            float a4[4] = {av.x, av.y, av.z, av.w};
#pragma unroll
            for (int j = 0; j < 4; j++) {
                float2 w2 = *(const float2*)(sWL0 + (4 * u4 + j) * 64 + 2 * lane);  // LDS.64
                y0  = fmaf(a4[j], w2.x, y0);
                y1v = fmaf(a4[j], w2.y, y1v);
            }
        }
        o[2 * lane]     = y0;
        o[2 * lane + 1] = y1v;
    }
    {   // y1[w',k] = sum_{u<64} a1a[u,k] WL1a[u,w'] + sum_{u<16} a1b[u,k] WL1b[u,w']
        float y[3] = {0.f, 0.f, 0.f};
#pragma unroll
        for (int u = 0; u < 64; u++) {
            float4 av = *(const float4*)(ag + 32 + 4 * u);        // broadcast LDS.128
            float lw = sWL1a[u * 32 + lane];
            y[0] = fmaf(av.x, lw, y[0]);
            y[1] = fmaf(av.y, lw, y[1]);
            y[2] = fmaf(av.z, lw, y[2]);
        }
#pragma unroll
        for (int u = 0; u < 16; u++) {
            float4 av = *(const float4*)(ag + 288 + 4 * u);       // broadcast LDS.128
            float lw = sWL1b[u * 32 + lane];
            y[0] = fmaf(av.x, lw, y[0]);
            y[1] = fmaf(av.y, lw, y[1]);
            y[2] = fmaf(av.z, lw, y[2]);
        }
#pragma unroll
        for (int k = 0; k < 3; k++) o[64 + 3 * lane + k] = y[k];
    }
    {   // y2[w',a] = sum_u a2[u,a] WL2[u,w'] — u-loop split across half-warps
        int w2i = lane & 15, half = lane >> 4;
        float y[5] = {0.f, 0.f, 0.f, 0.f, 0.f};
#pragma unroll
        for (int uu = 0; uu < 16; uu++) {
            int u = half * 16 + uu;
            float lw = sWL2[u * 16 + w2i];
#pragma unroll
            for (int a = 0; a < 5; a++) y[a] = fmaf(ag[352 + 5 * u + a], lw, y[a]);
        }
#pragma unroll
        for (int a = 0; a < 5; a++) {
            y[a] += __shfl_xor_sync(FULL, y[a], 16);
            if (lane < 16) o[160 + 5 * lane + a] = y[a];
        }
    }
}

// ============================================================================
extern "C" void kernel_launch(void* const* d_in, const int* in_sizes, int n_in,
                              void* d_out, int out_size) {
    const float* feats  = (const float*)d_in[0];  // (4,4096,240)
    const float* coords = (const float*)d_in[1];  // (4,4096,3)
    const float* W1 = (const float*)d_in[2];      // (64,32)
    const float* W2 = (const float*)d_in[3];      // (32,64)
    const float* W3 = (const float*)d_in[4];      // (32,16)
    const float* W4 = (const float*)d_in[5];      // (16,32)
    const float* L0 = (const float*)d_in[6];      // (64,64)
    const float* L1 = (const float*)d_in[7];      // (32,32)
    const float* L2 = (const float*)d_in[8];      // (16,16)
    float* out = (float*)d_out;

    repack_kernel<<<BN / 8, 256>>>(feats, coords);
    fuse_kernel<<<20, 256>>>(W1, W2, W3, W4, L0, L1, L2);
    knn_kernel<<<dim3(NNODES / KWARPS, NB), KTHREADS>>>();
    agg_kernel<<<BN / 8, 256>>>(out);
}